// round 2
// baseline (speedup 1.0000x reference)
#include <cuda_runtime.h>

// ---------------- problem constants ----------------
#define B_    64
#define N_    482
#define DIM_  512
#define H_    8
#define D_    64
#define QKV_  1536
#define BH_   (B_*H_)          // 512
#define BN_   (B_*N_)          // 30848  (== 241*128, exact for 128-tiles)
#define SZ_BND (BN_*DIM_)      // 15794176
#define NHW_  256
#define NB_   225
#define TAIL0_ 257             // N_ - NB_
#define SCALE_ 0.125f          // DIM_HEAD^-0.5

// ---------------- packed f32x2 helpers (FFMA2 path, sm_103a) ----------------
__device__ __forceinline__ double ffma2(double a, double b, double c) {
    double d;
    asm("fma.rn.f32x2 %0, %1, %2, %3;" : "=d"(d) : "d"(a), "d"(b), "d"(c));
    return d;
}
__device__ __forceinline__ float2 unpk(double d) {
    float2 r;
    asm("mov.b64 {%0, %1}, %2;" : "=f"(r.x), "=f"(r.y) : "d"(d));
    return r;
}

// ---------------- device scratch (static, allowed) ----------------
__device__ float g_qkv [(size_t)BN_*QKV_];
__device__ float g_qkvm[(size_t)BN_*QKV_];
__device__ float g_qq  [(size_t)BH_*N_*D_];
__device__ float g_kk  [(size_t)BH_*N_*D_];
__device__ float g_vv  [(size_t)BH_*N_*D_];
__device__ float g_vm  [(size_t)BH_*N_*D_];
__device__ float g_dots[(size_t)BH_*N_*N_];   // 512*482*482
__device__ float g_out [SZ_BND];
__device__ float g_m   [SZ_BND];
__device__ float g_out2[SZ_BND];
__device__ float g_m2  [SZ_BND];
__device__ float g_max [B_*H_*3*D_];
__device__ float g_upd [BN_];
__device__ float g_mm  [B_*(N_-1)];

// ---------------- generic NT SGEMM, 128x128 tile, packed f32x2 inner ----------
// C[m,n] = sum_k A[m*K+k] * f(B[n*K+k]) (+ bias[n]); K%8==0, M%128==0, N%128==0
template<bool ABS_B, bool BIAS>
__global__ void __launch_bounds__(256) sgemm128(const float* __restrict__ A,
                                                const float* __restrict__ Bm,
                                                const float* __restrict__ bias,
                                                float* __restrict__ C,
                                                int K, int ldc)
{
    __shared__ __align__(16) float As[8][256];   // duplicated pairs: elem e at [2e],[2e+1]
    __shared__ __align__(16) float Bs[8][128];
    const int tid = threadIdx.x;
    const int bm = blockIdx.y * 128, bn = blockIdx.x * 128;
    const int lr = tid >> 1, lk = (tid & 1) * 4;
    const float* Ap = A  + (size_t)(bm + lr) * K + lk;
    const float* Bp = Bm + (size_t)(bn + lr) * K + lk;
    const int tx = tid & 15, ty = tid >> 4;

    double acc[8][4];
    #pragma unroll
    for (int i = 0; i < 8; i++)
        #pragma unroll
        for (int j = 0; j < 4; j++) acc[i][j] = 0.0;

    for (int k0 = 0; k0 < K; k0 += 8) {
        float4 av = *(const float4*)(Ap + k0);
        float4 bv = *(const float4*)(Bp + k0);
        if (ABS_B) { bv.x = fabsf(bv.x); bv.y = fabsf(bv.y); bv.z = fabsf(bv.z); bv.w = fabsf(bv.w); }
        *(float2*)&As[lk+0][2*lr] = make_float2(av.x, av.x);
        *(float2*)&As[lk+1][2*lr] = make_float2(av.y, av.y);
        *(float2*)&As[lk+2][2*lr] = make_float2(av.z, av.z);
        *(float2*)&As[lk+3][2*lr] = make_float2(av.w, av.w);
        Bs[lk+0][lr] = bv.x; Bs[lk+1][lr] = bv.y; Bs[lk+2][lr] = bv.z; Bs[lk+3][lr] = bv.w;
        __syncthreads();
        #pragma unroll
        for (int k = 0; k < 8; k++) {
            double2 m01 = *(const double2*)&As[k][ty*8];
            double2 m23 = *(const double2*)&As[k][ty*8 + 4];
            double2 m45 = *(const double2*)&As[k][128 + ty*8];
            double2 m67 = *(const double2*)&As[k][128 + ty*8 + 4];
            double2 n01 = *(const double2*)&Bs[k][tx*4];
            double2 n23 = *(const double2*)&Bs[k][64 + tx*4];
            double rm[8] = {m01.x, m01.y, m23.x, m23.y, m45.x, m45.y, m67.x, m67.y};
            double rn[4] = {n01.x, n01.y, n23.x, n23.y};
            #pragma unroll
            for (int i = 0; i < 8; i++)
                #pragma unroll
                for (int j = 0; j < 4; j++) acc[i][j] = ffma2(rm[i], rn[j], acc[i][j]);
        }
        __syncthreads();
    }
    #pragma unroll
    for (int i = 0; i < 8; i++) {
        int m = bm + ((i < 4) ? ty*4 + i : 64 + ty*4 + (i-4));
        #pragma unroll
        for (int jh = 0; jh < 2; jh++) {
            int n = bn + jh*64 + tx*4;
            float2 lo = unpk(acc[i][jh*2]);
            float2 hi = unpk(acc[i][jh*2+1]);
            float4 r = make_float4(lo.x, lo.y, hi.x, hi.y);
            if (BIAS) { r.x += bias[n]; r.y += bias[n+1]; r.z += bias[n+2]; r.w += bias[n+3]; }
            *(float4*)&C[(size_t)m * ldc + n] = r;
        }
    }
}

// ---------------- updated[b,i] = (i==0) ? 1 : (sum(mask row) > 0) ----------------
__global__ void updated_k(const float* __restrict__ mask)
{
    int row = blockIdx.x * (blockDim.x >> 5) + (threadIdx.x >> 5);
    if (row >= BN_) return;
    int ln = threadIdx.x & 31;
    const float* p = mask + (size_t)row * DIM_;
    float s = 0.f;
    #pragma unroll
    for (int e = ln; e < DIM_; e += 32) s += p[e];
    #pragma unroll
    for (int o = 16; o > 0; o >>= 1) s += __shfl_xor_sync(0xffffffffu, s, o);
    if (ln == 0) {
        int i = row % N_;
        g_upd[row] = (i == 0) ? 1.0f : (s > 0.0f ? 1.0f : 0.0f);
    }
}

// ---------------- per-(b,h,w,d) max over sequence of qkv_m ----------------
__global__ void reduce_max_k()
{
    int o = blockIdx.x * blockDim.x + threadIdx.x;
    if (o >= B_*H_*3*D_) return;
    int d = o & 63;
    int w = (o >> 6) % 3;
    int h = ((o >> 6) / 3) % H_;
    int b = (o >> 6) / 24;
    const float* p = g_qkvm + (size_t)b * N_ * QKV_ + w * DIM_ + h * 64 + d;
    float mx = -1e30f;
    for (int i = 0; i < N_; i++) mx = fmaxf(mx, p[(size_t)i * QKV_]);
    g_max[o] = mx;   // layout [b][h][w][d]
}

// ---------------- build modulated q,k,v tensors in [b,h,n,d] ----------------
__global__ void modulate_k()
{
    int idx = blockIdx.x * blockDim.x + threadIdx.x;
    if (idx >= SZ_BND) return;
    int hd = idx % DIM_;
    int i  = (idx / DIM_) % N_;
    int b  = idx / (DIM_ * N_);
    int h = hd >> 6, d = hd & 63;
    size_t base = (size_t)(b * N_ + i) * QKV_;
    float q  = g_qkv [base + hd];
    float k  = g_qkv [base + DIM_ + hd];
    float v  = g_qkv [base + 2*DIM_ + hd];
    float qm = g_qkvm[base + hd];
    float km = g_qkvm[base + DIM_ + hd];
    float vm = g_qkvm[base + 2*DIM_ + hd];
    int mb = ((b * H_ + h) * 3) * 64 + d;
    float qmn = qm / (1e-6f + g_max[mb]);
    float kmn = km / (1e-6f + g_max[mb + 64]);
    float vmn = vm / (1e-6f + g_max[mb + 128]);
    size_t o = ((size_t)(b * H_ + h) * N_ + i) * D_ + d;
    g_qq[o] = q * qmn * SCALE_;   // fold softmax scale into q side
    g_kk[o] = k * kmn;
    g_vv[o] = v * vmn;
    g_vm[o] = vmn;
}

// ---------------- batched NT GEMM: dots[bh] = qq @ kk^T (K=64), packed ----------
__global__ void __launch_bounds__(256) dots_gemm()
{
    int bh = blockIdx.z;
    const float* A  = g_qq + (size_t)bh * (N_ * D_);
    const float* Bm = g_kk + (size_t)bh * (N_ * D_);
    float* C = g_dots + (size_t)bh * N_ * N_;
    int bm = blockIdx.y * 128, bn = blockIdx.x * 128;
    __shared__ __align__(16) float As[8][256];
    __shared__ __align__(16) float Bs[8][128];
    const int tid = threadIdx.x, lr = tid >> 1, lk = (tid & 1) * 4;
    const int ar = bm + lr, br = bn + lr;
    const int tx = tid & 15, ty = tid >> 4;

    double acc[8][4];
    #pragma unroll
    for (int i = 0; i < 8; i++)
        #pragma unroll
        for (int j = 0; j < 4; j++) acc[i][j] = 0.0;

    #pragma unroll
    for (int k0 = 0; k0 < D_; k0 += 8) {
        float4 av = make_float4(0.f,0.f,0.f,0.f);
        float4 bv = make_float4(0.f,0.f,0.f,0.f);
        if (ar < N_) av = *(const float4*)(A  + (size_t)ar * D_ + k0 + lk);
        if (br < N_) bv = *(const float4*)(Bm + (size_t)br * D_ + k0 + lk);
        *(float2*)&As[lk+0][2*lr] = make_float2(av.x, av.x);
        *(float2*)&As[lk+1][2*lr] = make_float2(av.y, av.y);
        *(float2*)&As[lk+2][2*lr] = make_float2(av.z, av.z);
        *(float2*)&As[lk+3][2*lr] = make_float2(av.w, av.w);
        Bs[lk+0][lr] = bv.x; Bs[lk+1][lr] = bv.y; Bs[lk+2][lr] = bv.z; Bs[lk+3][lr] = bv.w;
        __syncthreads();
        #pragma unroll
        for (int k = 0; k < 8; k++) {
            double2 m01 = *(const double2*)&As[k][ty*8];
            double2 m23 = *(const double2*)&As[k][ty*8 + 4];
            double2 m45 = *(const double2*)&As[k][128 + ty*8];
            double2 m67 = *(const double2*)&As[k][128 + ty*8 + 4];
            double2 n01 = *(const double2*)&Bs[k][tx*4];
            double2 n23 = *(const double2*)&Bs[k][64 + tx*4];
            double rm[8] = {m01.x, m01.y, m23.x, m23.y, m45.x, m45.y, m67.x, m67.y};
            double rn[4] = {n01.x, n01.y, n23.x, n23.y};
            #pragma unroll
            for (int i = 0; i < 8; i++)
                #pragma unroll
                for (int j = 0; j < 4; j++) acc[i][j] = ffma2(rm[i], rn[j], acc[i][j]);
        }
        __syncthreads();
    }
    #pragma unroll
    for (int i = 0; i < 8; i++) {
        int m = bm + ((i < 4) ? ty*4 + i : 64 + ty*4 + (i-4));
        if (m < N_) {
            #pragma unroll
            for (int jh = 0; jh < 2; jh++) {
                int n = bn + jh*64 + tx*4;
                float2 lo = unpk(acc[i][jh*2]);
                float2 hi = unpk(acc[i][jh*2+1]);
                float rr[4] = {lo.x, lo.y, hi.x, hi.y};
                #pragma unroll
                for (int jj = 0; jj < 4; jj++)
                    if (n + jj < N_) C[(size_t)m * N_ + n + jj] = rr[jj];
            }
        }
    }
}

// ---------------- row softmax over 482 elements (one block per row) ----------------
__global__ void __launch_bounds__(128) softmax_rows()
{
    size_t row = blockIdx.x;
    float* p = g_dots + row * N_;
    int tid = threadIdx.x;
    float v[4];
    float mx = -1e30f;
    #pragma unroll
    for (int e = 0; e < 4; e++) {
        int j = tid + e * 128;
        if (j < N_) { v[e] = p[j]; mx = fmaxf(mx, v[e]); } else v[e] = -1e30f;
    }
    #pragma unroll
    for (int o = 16; o > 0; o >>= 1) mx = fmaxf(mx, __shfl_xor_sync(0xffffffffu, mx, o));
    __shared__ float smax[4], ssum[4];
    int w = tid >> 5, ln = tid & 31;
    if (ln == 0) smax[w] = mx;
    __syncthreads();
    mx = fmaxf(fmaxf(smax[0], smax[1]), fmaxf(smax[2], smax[3]));
    float sum = 0.f;
    #pragma unroll
    for (int e = 0; e < 4; e++) {
        int j = tid + e * 128;
        if (j < N_) { v[e] = __expf(v[e] - mx); sum += v[e]; }
    }
    #pragma unroll
    for (int o = 16; o > 0; o >>= 1) sum += __shfl_xor_sync(0xffffffffu, sum, o);
    if (ln == 0) ssum[w] = sum;
    __syncthreads();
    float inv = 1.0f / (ssum[0] + ssum[1] + ssum[2] + ssum[3]);
    #pragma unroll
    for (int e = 0; e < 4; e++) {
        int j = tid + e * 128;
        if (j < N_) p[j] = v[e] * inv;
    }
}

// ---------------- PV: out = attn@(v*vm), m = attn@vm, packed f32x2 ---------------
__global__ void __launch_bounds__(256) attn_pv()
{
    int bh = blockIdx.y;
    int b = bh >> 3, h = bh & 7;
    int i0 = blockIdx.x * 128;
    const float* P  = g_dots + (size_t)bh * N_ * N_;
    const float* Vv = g_vv   + (size_t)bh * N_ * D_;
    const float* Vm = g_vm   + (size_t)bh * N_ * D_;
    __shared__ __align__(16) float Ps [16][260];   // duplicated pairs along row dim
    __shared__ __align__(16) float Vvs[16][64];
    __shared__ __align__(16) float Vms[16][64];
    int tid = threadIdx.x;
    int tx = tid & 15, ty = tid >> 4;

    double a1[8][2], a2[8][2];
    #pragma unroll
    for (int i = 0; i < 8; i++)
        #pragma unroll
        for (int j = 0; j < 2; j++) { a1[i][j] = 0.0; a2[i][j] = 0.0; }

    for (int j0 = 0; j0 < N_; j0 += 16) {
        #pragma unroll
        for (int e = 0; e < 8; e++) {
            int t = tid + e * 256;
            int r = t >> 4, j = t & 15;
            float val = 0.f;
            if (i0 + r < N_ && j0 + j < N_) val = P[(size_t)(i0 + r) * N_ + j0 + j];
            *(float2*)&Ps[j][2*r] = make_float2(val, val);
        }
        #pragma unroll
        for (int e = 0; e < 4; e++) {
            int t = tid + e * 256;
            int j = t >> 6, d = t & 63;
            float v1 = 0.f, v2 = 0.f;
            if (j0 + j < N_) {
                v1 = Vv[(size_t)(j0 + j) * D_ + d];
                v2 = Vm[(size_t)(j0 + j) * D_ + d];
            }
            Vvs[j][d] = v1; Vms[j][d] = v2;
        }
        __syncthreads();
        #pragma unroll
        for (int k = 0; k < 16; k++) {
            double2 m01 = *(const double2*)&Ps[k][ty*8];
            double2 m23 = *(const double2*)&Ps[k][ty*8 + 4];
            double2 m45 = *(const double2*)&Ps[k][128 + ty*8];
            double2 m67 = *(const double2*)&Ps[k][128 + ty*8 + 4];
            double2 v1 = *(const double2*)&Vvs[k][tx*4];
            double2 v2 = *(const double2*)&Vms[k][tx*4];
            double rm[8] = {m01.x, m01.y, m23.x, m23.y, m45.x, m45.y, m67.x, m67.y};
            #pragma unroll
            for (int i = 0; i < 8; i++) {
                a1[i][0] = ffma2(rm[i], v1.x, a1[i][0]);
                a1[i][1] = ffma2(rm[i], v1.y, a1[i][1]);
                a2[i][0] = ffma2(rm[i], v2.x, a2[i][0]);
                a2[i][1] = ffma2(rm[i], v2.y, a2[i][1]);
            }
        }
        __syncthreads();
    }
    #pragma unroll
    for (int i = 0; i < 8; i++) {
        int ii = (i < 4) ? ty*4 + i : 64 + ty*4 + (i-4);
        int gi = i0 + ii;
        if (gi < N_) {
            float u = g_upd[b * N_ + gi];
            size_t base = (size_t)(b * N_ + gi) * DIM_ + h * 64 + tx * 4;
            float2 p0 = unpk(a1[i][0]), p1 = unpk(a1[i][1]);
            float2 q0 = unpk(a2[i][0]), q1 = unpk(a2[i][1]);
            float4 r1 = make_float4(p0.x*u, p0.y*u, p1.x*u, p1.y*u);
            float4 r2 = make_float4(q0.x*u, q0.y*u, q1.x*u, q1.y*u);
            *(float4*)&g_out[base] = r1;
            *(float4*)&g_m  [base] = r2;
        }
    }
}

// ---------------- overlap blending: out2/m2 = out/m + origin/bridge additions ------
__global__ void blend_k()
{
    int idx = blockIdx.x * blockDim.x + threadIdx.x;
    if (idx >= SZ_BND) return;
    int c = idx % DIM_;
    int i = (idx / DIM_) % N_;
    int b = idx / (DIM_ * N_);
    float o = g_out[idx], mv = g_m[idx];
    if (i >= 1 && i <= NHW_) {
        int p = i - 1, y = p >> 4, x = p & 15;
        float inv = 1.0f - g_upd[b * N_ + i];
        float s1 = 0.f, s2 = 0.f;
        #pragma unroll
        for (int dy = -1; dy <= 0; dy++)
            #pragma unroll
            for (int dx = -1; dx <= 0; dx++) {
                int r = y + dy, cc = x + dx;
                if (r >= 0 && r < 15 && cc >= 0 && cc < 15) {
                    size_t src = ((size_t)(b * N_ + TAIL0_ + r * 15 + cc)) * DIM_ + c;
                    s1 += g_out[src]; s2 += g_m[src];
                }
            }
        o  += 0.25f * s1 * inv;
        mv += 0.25f * s2 * inv;
    } else if (i >= TAIL0_) {
        int p = i - TAIL0_, r = p / 15, cc = p % 15;
        float inv = 1.0f - g_upd[b * N_ + i];
        float s1 = 0.f, s2 = 0.f;
        #pragma unroll
        for (int dy = 0; dy <= 1; dy++)
            #pragma unroll
            for (int dx = 0; dx <= 1; dx++) {
                size_t src = ((size_t)(b * N_ + 1 + (r + dy) * 16 + (cc + dx))) * DIM_ + c;
                s1 += g_out[src]; s2 += g_m[src];
            }
        o  += 0.25f * s1 * inv;
        mv += 0.25f * s2 * inv;
    }
    g_out2[idx] = o;
    g_m2[idx] = mv;
}

// ---------------- mm[b,j] = mean over channels of m2[b, j+1, :] ----------------
__global__ void mm_k()
{
    int row = blockIdx.x * (blockDim.x >> 5) + (threadIdx.x >> 5);
    if (row >= B_ * (N_ - 1)) return;
    int b = row / (N_ - 1), j = row % (N_ - 1);
    int ln = threadIdx.x & 31;
    const float* p = g_m2 + (size_t)(b * N_ + j + 1) * DIM_;
    float s = 0.f;
    #pragma unroll
    for (int e = ln; e < DIM_; e += 32) s += p[e];
    #pragma unroll
    for (int o = 16; o > 0; o >>= 1) s += __shfl_xor_sync(0xffffffffu, s, o);
    if (ln == 0) g_mm[row] = s * (1.0f / DIM_);
}

// ---------------- inter: NN upsample + center blend, [B,256,256] ----------------
__global__ void inter_k(float* __restrict__ outp)
{
    int idx = blockIdx.x * blockDim.x + threadIdx.x;
    if (idx >= B_ * 256 * 256) return;
    int x = idx & 255, y = (idx >> 8) & 255, b = idx >> 16;
    float v = g_mm[b * (N_ - 1) + (y >> 4) * 16 + (x >> 4)];
    if (y >= 8 && y < 248 && x >= 8 && x < 248) {
        float sh = g_mm[b * (N_ - 1) + 256 + ((y - 8) >> 4) * 15 + ((x - 8) >> 4)];
        v = 0.5f * (v + sh);
    }
    outp[idx] = v;
}

// ---------------- launch ----------------
extern "C" void kernel_launch(void* const* d_in, const int* in_sizes, int n_in,
                              void* d_out, int out_size)
{
    const float* x    = (const float*)d_in[0];
    const float* mask = (const float*)d_in[1];
    const float* Wqkv = (const float*)d_in[2];
    const float* Wout = (const float*)d_in[3];
    const float* bout = (const float*)d_in[4];
    float* out = (float*)d_out;

    float *p_qkv, *p_qkvm, *p_out2, *p_m2;
    cudaGetSymbolAddress((void**)&p_qkv,  g_qkv);
    cudaGetSymbolAddress((void**)&p_qkvm, g_qkvm);
    cudaGetSymbolAddress((void**)&p_out2, g_out2);
    cudaGetSymbolAddress((void**)&p_m2,   g_m2);

    // 1-2. qkv = x @ Wqkv^T ; qkv_m = mask @ |Wqkv|^T
    sgemm128<false,false><<<dim3(QKV_/128, BN_/128), 256>>>(x,    Wqkv, nullptr, p_qkv,  DIM_, QKV_);
    sgemm128<true, false><<<dim3(QKV_/128, BN_/128), 256>>>(mask, Wqkv, nullptr, p_qkvm, DIM_, QKV_);
    // 3. updated flags
    updated_k<<<(BN_ + 7) / 8, 256>>>(mask);
    // 4. per-(b,h,w,d) sequence maxima of qkv_m
    reduce_max_k<<<(B_*H_*3*D_ + 255) / 256, 256>>>();
    // 5. modulated q,k,v in head-major layout
    modulate_k<<<(SZ_BND + 255) / 256, 256>>>();
    // 6. scores
    dots_gemm<<<dim3(4, 4, BH_), 256>>>();
    // 7. softmax
    softmax_rows<<<BH_ * N_, 128>>>();
    // 8. PV (out and m together), *updated, scatter to [B,n,512]
    attn_pv<<<dim3(4, BH_), 256>>>();
    // 9. overlap blending
    blend_k<<<(SZ_BND + 255) / 256, 256>>>();
    // 10. channel means of blended m
    mm_k<<<(B_ * (N_ - 1) + 7) / 8, 256>>>();
    // 11. inter output
    inter_k<<<(B_ * 65536 + 255) / 256, 256>>>(out + 2 * (size_t)SZ_BND);
    // 12-13. final projections straight into d_out
    sgemm128<false,true ><<<dim3(DIM_/128, BN_/128), 256>>>(p_out2, Wout, bout,    out,                    DIM_, DIM_);
    sgemm128<true, false><<<dim3(DIM_/128, BN_/128), 256>>>(p_m2,   Wout, nullptr, out + (size_t)SZ_BND,   DIM_, DIM_);
}

// round 4
// speedup vs baseline: 1.2229x; 1.2229x over previous
#include <cuda_runtime.h>
#include <cstdint>

// ---------------- problem constants ----------------
#define B_    64
#define N_    482
#define DIM_  512
#define H_    8
#define D_    64
#define QKV_  1536
#define BH_   (B_*H_)          // 512
#define BN_   (B_*N_)          // 30848  (== 241*128)
#define SZ_BND (BN_*DIM_)      // 15794176
#define NHW_  256
#define NB_   225
#define TAIL0_ 257             // N_ - NB_
#define SCALE_ 0.125f
#define LDP_  512              // padded leading dim for dots (16B alignment)

// ---------------- device scratch ----------------
__device__ float g_qkv [(size_t)BN_*QKV_];
__device__ float g_qkvm[(size_t)BN_*QKV_];
__device__ float g_qq  [(size_t)BH_*N_*D_];
__device__ float g_kk  [(size_t)BH_*N_*D_];
__device__ float g_vv  [(size_t)BH_*N_*D_];
__device__ float g_vm  [(size_t)BH_*N_*D_];
__device__ float g_dots[(size_t)BH_*N_*LDP_];
__device__ float g_out [SZ_BND];
__device__ float g_m   [SZ_BND];
__device__ float g_out2[SZ_BND];
__device__ float g_m2  [SZ_BND];
__device__ float g_max [B_*H_*3*D_];
__device__ float g_upd [BN_];
__device__ float g_mm  [B_*(N_-1)];

// ---------------- tf32 mma helpers ----------------
__device__ __forceinline__ void mma_tf32(float* c, const uint32_t* a, const uint32_t* b) {
    asm volatile("mma.sync.aligned.m16n8k8.row.col.f32.tf32.tf32.f32 "
        "{%0,%1,%2,%3}, {%4,%5,%6,%7}, {%8,%9}, {%0,%1,%2,%3};"
        : "+f"(c[0]), "+f"(c[1]), "+f"(c[2]), "+f"(c[3])
        : "r"(a[0]), "r"(a[1]), "r"(a[2]), "r"(a[3]), "r"(b[0]), "r"(b[1]));
}
__device__ __forceinline__ void split_tf32(float x, uint32_t& hi, uint32_t& lo) {
    uint32_t h;
    asm("cvt.rna.tf32.f32 %0, %1;" : "=r"(h) : "f"(x));
    float l = x - __uint_as_float(h);
    uint32_t lr;
    asm("cvt.rna.tf32.f32 %0, %1;" : "=r"(lr) : "f"(l));
    hi = h; lo = lr;
}

// ================= generic tf32x3 NT GEMM, 128x128 tile =================
// C[m,n] = sum_k A[m*lda+k] * f(B[n*ldb+k]) (+bias[n]); batched via blockIdx.z
template<bool ABS_B, bool BIAS, bool BOUND>
__global__ void __launch_bounds__(256) mma_gemm(const float* __restrict__ A,
                                                const float* __restrict__ Bm,
                                                const float* __restrict__ bias,
                                                float* __restrict__ C,
                                                int M, int N, int K,
                                                int lda, int ldb, int ldc,
                                                long long sA, long long sB, long long sC)
{
    __shared__ float As[128][36];
    __shared__ float Bs[128][36];
    A  += (long long)blockIdx.z * sA;
    Bm += (long long)blockIdx.z * sB;
    C  += (long long)blockIdx.z * sC;
    const int tid = threadIdx.x;
    const int bm = blockIdx.y * 128, bn = blockIdx.x * 128;
    const int lane = tid & 31, wid = tid >> 5;
    const int gr = lane >> 2, gc = lane & 3;
    const int wm = (wid & 1) * 64, wn = (wid >> 1) * 32;
    const int lr = tid >> 3, lc = (tid & 7) * 4;

    float acc[4][4][4];
    #pragma unroll
    for (int i = 0; i < 4; i++)
        #pragma unroll
        for (int j = 0; j < 4; j++)
            #pragma unroll
            for (int e = 0; e < 4; e++) acc[i][j][e] = 0.f;

    for (int kt = 0; kt < K; kt += 32) {
        #pragma unroll
        for (int r = 0; r < 4; r++) {
            int row = lr + r * 32;
            float4 av = make_float4(0.f,0.f,0.f,0.f);
            float4 bv = make_float4(0.f,0.f,0.f,0.f);
            if (!BOUND || bm + row < M) av = *(const float4*)(A  + (size_t)(bm + row) * lda + kt + lc);
            if (!BOUND || bn + row < N) bv = *(const float4*)(Bm + (size_t)(bn + row) * ldb + kt + lc);
            if (ABS_B) { bv.x = fabsf(bv.x); bv.y = fabsf(bv.y); bv.z = fabsf(bv.z); bv.w = fabsf(bv.w); }
            *(float4*)&As[row][lc] = av;
            *(float4*)&Bs[row][lc] = bv;
        }
        __syncthreads();
        #pragma unroll
        for (int ks = 0; ks < 4; ks++) {
            const int k0 = ks * 8;
            uint32_t ah[4][4], al[4][4], bh[4][2], bl[4][2];
            #pragma unroll
            for (int mt = 0; mt < 4; mt++) {
                int r0 = wm + mt * 16 + gr;
                split_tf32(As[r0    ][k0 + gc    ], ah[mt][0], al[mt][0]);
                split_tf32(As[r0 + 8][k0 + gc    ], ah[mt][1], al[mt][1]);
                split_tf32(As[r0    ][k0 + gc + 4], ah[mt][2], al[mt][2]);
                split_tf32(As[r0 + 8][k0 + gc + 4], ah[mt][3], al[mt][3]);
            }
            #pragma unroll
            for (int nt = 0; nt < 4; nt++) {
                int c0 = wn + nt * 8 + gr;
                split_tf32(Bs[c0][k0 + gc    ], bh[nt][0], bl[nt][0]);
                split_tf32(Bs[c0][k0 + gc + 4], bh[nt][1], bl[nt][1]);
            }
            #pragma unroll
            for (int mt = 0; mt < 4; mt++)
                #pragma unroll
                for (int nt = 0; nt < 4; nt++) {
                    mma_tf32(acc[mt][nt], ah[mt], bl[nt]);
                    mma_tf32(acc[mt][nt], al[mt], bh[nt]);
                    mma_tf32(acc[mt][nt], ah[mt], bh[nt]);
                }
        }
        __syncthreads();
    }
    #pragma unroll
    for (int mt = 0; mt < 4; mt++)
        #pragma unroll
        for (int nt = 0; nt < 4; nt++) {
            int m0 = bm + wm + mt * 16 + gr;
            int n0 = bn + wn + nt * 8 + gc * 2;
            float bx = 0.f, by = 0.f;
            if (BIAS) { bx = bias[n0]; by = bias[n0 + 1]; }
            if ((!BOUND || (m0 < M && n0 < N)))
                *(float2*)&C[(size_t)m0 * ldc + n0] = make_float2(acc[mt][nt][0] + bx, acc[mt][nt][1] + by);
            if ((!BOUND || (m0 + 8 < M && n0 < N)))
                *(float2*)&C[(size_t)(m0 + 8) * ldc + n0] = make_float2(acc[mt][nt][2] + bx, acc[mt][nt][3] + by);
        }
}

// ================= PV tf32x3: out = P@(v*vm), m = P@vm =================
__global__ void __launch_bounds__(256) attn_pv_mma()
{
    const int bh = blockIdx.y;
    const int b = bh >> 3, h = bh & 7;
    const int i0 = blockIdx.x * 128;
    const float* P  = g_dots + (size_t)bh * N_ * LDP_;
    const float* Vv = g_vv   + (size_t)bh * N_ * D_;
    const float* Vm = g_vm   + (size_t)bh * N_ * D_;
    __shared__ float Ps[128][36];
    __shared__ float V1[32][72];
    __shared__ float V2[32][72];
    const int tid = threadIdx.x;
    const int lane = tid & 31, wid = tid >> 5;
    const int gr = lane >> 2, gc = lane & 3;
    const int wm = (wid >> 1) * 32, wn = (wid & 1) * 32;

    float acc1[2][4][4], acc2[2][4][4];
    #pragma unroll
    for (int i = 0; i < 2; i++)
        #pragma unroll
        for (int j = 0; j < 4; j++)
            #pragma unroll
            for (int e = 0; e < 4; e++) { acc1[i][j][e] = 0.f; acc2[i][j][e] = 0.f; }

    for (int j0 = 0; j0 < N_; j0 += 32) {
        {   // P tile: 128 x 32  (ld = LDP_ = 512, 16B aligned)
            int lr = tid >> 3, lc = (tid & 7) * 4;
            #pragma unroll
            for (int r = 0; r < 4; r++) {
                int row = lr + r * 32;
                float4 pv = make_float4(0.f,0.f,0.f,0.f);
                if (i0 + row < N_) {
                    pv = *(const float4*)(P + (size_t)(i0 + row) * LDP_ + j0 + lc);
                    // zero the padded tail columns (j >= N_)
                    if (j0 + lc + 3 >= N_) {
                        if (j0 + lc + 0 >= N_) pv.x = 0.f;
                        if (j0 + lc + 1 >= N_) pv.y = 0.f;
                        if (j0 + lc + 2 >= N_) pv.z = 0.f;
                        if (j0 + lc + 3 >= N_) pv.w = 0.f;
                    }
                }
                *(float4*)&Ps[row][lc] = pv;
            }
        }
        {   // V tiles: 32 x 64
            int r = tid >> 4, c = (tid & 15) * 4;
            #pragma unroll
            for (int e = 0; e < 2; e++) {
                int row = r + e * 16;
                float4 v1 = make_float4(0.f,0.f,0.f,0.f);
                float4 v2 = make_float4(0.f,0.f,0.f,0.f);
                if (j0 + row < N_) {
                    v1 = *(const float4*)(Vv + (size_t)(j0 + row) * D_ + c);
                    v2 = *(const float4*)(Vm + (size_t)(j0 + row) * D_ + c);
                }
                *(float4*)&V1[row][c] = v1;
                *(float4*)&V2[row][c] = v2;
            }
        }
        __syncthreads();
        #pragma unroll
        for (int ks = 0; ks < 4; ks++) {
            const int k0 = ks * 8;
            uint32_t ah[2][4], al[2][4];
            #pragma unroll
            for (int mt = 0; mt < 2; mt++) {
                int r0 = wm + mt * 16 + gr;
                split_tf32(Ps[r0    ][k0 + gc    ], ah[mt][0], al[mt][0]);
                split_tf32(Ps[r0 + 8][k0 + gc    ], ah[mt][1], al[mt][1]);
                split_tf32(Ps[r0    ][k0 + gc + 4], ah[mt][2], al[mt][2]);
                split_tf32(Ps[r0 + 8][k0 + gc + 4], ah[mt][3], al[mt][3]);
            }
            #pragma unroll
            for (int nt = 0; nt < 4; nt++) {
                int c0 = wn + nt * 8 + gr;
                uint32_t bh0[2], bl0[2];
                split_tf32(V1[k0 + gc    ][c0], bh0[0], bl0[0]);
                split_tf32(V1[k0 + gc + 4][c0], bh0[1], bl0[1]);
                #pragma unroll
                for (int mt = 0; mt < 2; mt++) {
                    mma_tf32(acc1[mt][nt], ah[mt], bl0);
                    mma_tf32(acc1[mt][nt], al[mt], bh0);
                    mma_tf32(acc1[mt][nt], ah[mt], bh0);
                }
                split_tf32(V2[k0 + gc    ][c0], bh0[0], bl0[0]);
                split_tf32(V2[k0 + gc + 4][c0], bh0[1], bl0[1]);
                #pragma unroll
                for (int mt = 0; mt < 2; mt++) {
                    mma_tf32(acc2[mt][nt], ah[mt], bl0);
                    mma_tf32(acc2[mt][nt], al[mt], bh0);
                    mma_tf32(acc2[mt][nt], ah[mt], bh0);
                }
            }
        }
        __syncthreads();
    }
    #pragma unroll
    for (int mt = 0; mt < 2; mt++)
        #pragma unroll
        for (int nt = 0; nt < 4; nt++) {
            int d = wn + nt * 8 + gc * 2;
            #pragma unroll
            for (int half = 0; half < 2; half++) {
                int gi = i0 + wm + mt * 16 + gr + half * 8;
                if (gi < N_) {
                    float u = g_upd[b * N_ + gi];
                    size_t base = (size_t)(b * N_ + gi) * DIM_ + h * 64 + d;
                    *(float2*)&g_out[base] = make_float2(acc1[mt][nt][half*2]*u, acc1[mt][nt][half*2+1]*u);
                    *(float2*)&g_m  [base] = make_float2(acc2[mt][nt][half*2]*u, acc2[mt][nt][half*2+1]*u);
                }
            }
        }
}

// ---------------- updated[b,i] ----------------
__global__ void updated_k(const float* __restrict__ mask)
{
    int row = blockIdx.x * (blockDim.x >> 5) + (threadIdx.x >> 5);
    if (row >= BN_) return;
    int ln = threadIdx.x & 31;
    const float* p = mask + (size_t)row * DIM_;
    float s = 0.f;
    #pragma unroll
    for (int e = ln; e < DIM_; e += 32) s += p[e];
    #pragma unroll
    for (int o = 16; o > 0; o >>= 1) s += __shfl_xor_sync(0xffffffffu, s, o);
    if (ln == 0) {
        int i = row % N_;
        g_upd[row] = (i == 0) ? 1.0f : (s > 0.0f ? 1.0f : 0.0f);
    }
}

// ---------------- per-(b,h,w,d) max over sequence ----------------
__global__ void reduce_max_k()
{
    int o = blockIdx.x * blockDim.x + threadIdx.x;
    if (o >= B_*H_*3*D_) return;
    int d = o & 63;
    int w = (o >> 6) % 3;
    int h = ((o >> 6) / 3) % H_;
    int b = (o >> 6) / 24;
    const float* p = g_qkvm + (size_t)b * N_ * QKV_ + w * DIM_ + h * 64 + d;
    float mx = -1e30f;
    for (int i = 0; i < N_; i++) mx = fmaxf(mx, p[(size_t)i * QKV_]);
    g_max[o] = mx;
}

// ---------------- modulated q,k,v ----------------
__global__ void modulate_k()
{
    int idx = blockIdx.x * blockDim.x + threadIdx.x;
    if (idx >= SZ_BND) return;
    int hd = idx % DIM_;
    int i  = (idx / DIM_) % N_;
    int b  = idx / (DIM_ * N_);
    int h = hd >> 6, d = hd & 63;
    size_t base = (size_t)(b * N_ + i) * QKV_;
    float q  = g_qkv [base + hd];
    float k  = g_qkv [base + DIM_ + hd];
    float v  = g_qkv [base + 2*DIM_ + hd];
    float qm = g_qkvm[base + hd];
    float km = g_qkvm[base + DIM_ + hd];
    float vm = g_qkvm[base + 2*DIM_ + hd];
    int mb = ((b * H_ + h) * 3) * 64 + d;
    float qmn = qm / (1e-6f + g_max[mb]);
    float kmn = km / (1e-6f + g_max[mb + 64]);
    float vmn = vm / (1e-6f + g_max[mb + 128]);
    size_t o = ((size_t)(b * H_ + h) * N_ + i) * D_ + d;
    g_qq[o] = q * qmn * SCALE_;
    g_kk[o] = k * kmn;
    g_vv[o] = v * vmn;
    g_vm[o] = vmn;
}

// ---------------- softmax (stride LDP_) ----------------
__global__ void __launch_bounds__(128) softmax_rows()
{
    size_t row = blockIdx.x;
    float* p = g_dots + row * LDP_;
    int tid = threadIdx.x;
    float v[4];
    float mx = -1e30f;
    #pragma unroll
    for (int e = 0; e < 4; e++) {
        int j = tid + e * 128;
        if (j < N_) { v[e] = p[j]; mx = fmaxf(mx, v[e]); } else v[e] = -1e30f;
    }
    #pragma unroll
    for (int o = 16; o > 0; o >>= 1) mx = fmaxf(mx, __shfl_xor_sync(0xffffffffu, mx, o));
    __shared__ float smax[4], ssum[4];
    int w = tid >> 5, ln = tid & 31;
    if (ln == 0) smax[w] = mx;
    __syncthreads();
    mx = fmaxf(fmaxf(smax[0], smax[1]), fmaxf(smax[2], smax[3]));
    float sum = 0.f;
    #pragma unroll
    for (int e = 0; e < 4; e++) {
        int j = tid + e * 128;
        if (j < N_) { v[e] = __expf(v[e] - mx); sum += v[e]; }
    }
    #pragma unroll
    for (int o = 16; o > 0; o >>= 1) sum += __shfl_xor_sync(0xffffffffu, sum, o);
    if (ln == 0) ssum[w] = sum;
    __syncthreads();
    float inv = 1.0f / (ssum[0] + ssum[1] + ssum[2] + ssum[3]);
    #pragma unroll
    for (int e = 0; e < 4; e++) {
        int j = tid + e * 128;
        if (j < N_) p[j] = v[e] * inv;
    }
}

// ---------------- overlap blending ----------------
__global__ void blend_k()
{
    int idx = blockIdx.x * blockDim.x + threadIdx.x;
    if (idx >= SZ_BND) return;
    int c = idx % DIM_;
    int i = (idx / DIM_) % N_;
    int b = idx / (DIM_ * N_);
    float o = g_out[idx], mv = g_m[idx];
    if (i >= 1 && i <= NHW_) {
        int p = i - 1, y = p >> 4, x = p & 15;
        float inv = 1.0f - g_upd[b * N_ + i];
        float s1 = 0.f, s2 = 0.f;
        #pragma unroll
        for (int dy = -1; dy <= 0; dy++)
            #pragma unroll
            for (int dx = -1; dx <= 0; dx++) {
                int r = y + dy, cc = x + dx;
                if (r >= 0 && r < 15 && cc >= 0 && cc < 15) {
                    size_t src = ((size_t)(b * N_ + TAIL0_ + r * 15 + cc)) * DIM_ + c;
                    s1 += g_out[src]; s2 += g_m[src];
                }
            }
        o  += 0.25f * s1 * inv;
        mv += 0.25f * s2 * inv;
    } else if (i >= TAIL0_) {
        int p = i - TAIL0_, r = p / 15, cc = p % 15;
        float inv = 1.0f - g_upd[b * N_ + i];
        float s1 = 0.f, s2 = 0.f;
        #pragma unroll
        for (int dy = 0; dy <= 1; dy++)
            #pragma unroll
            for (int dx = 0; dx <= 1; dx++) {
                size_t src = ((size_t)(b * N_ + 1 + (r + dy) * 16 + (cc + dx))) * DIM_ + c;
                s1 += g_out[src]; s2 += g_m[src];
            }
        o  += 0.25f * s1 * inv;
        mv += 0.25f * s2 * inv;
    }
    g_out2[idx] = o;
    g_m2[idx] = mv;
}

// ---------------- channel means ----------------
__global__ void mm_k()
{
    int row = blockIdx.x * (blockDim.x >> 5) + (threadIdx.x >> 5);
    if (row >= B_ * (N_ - 1)) return;
    int b = row / (N_ - 1), j = row % (N_ - 1);
    int ln = threadIdx.x & 31;
    const float* p = g_m2 + (size_t)(b * N_ + j + 1) * DIM_;
    float s = 0.f;
    #pragma unroll
    for (int e = ln; e < DIM_; e += 32) s += p[e];
    #pragma unroll
    for (int o = 16; o > 0; o >>= 1) s += __shfl_xor_sync(0xffffffffu, s, o);
    if (ln == 0) g_mm[row] = s * (1.0f / DIM_);
}

// ---------------- inter ----------------
__global__ void inter_k(float* __restrict__ outp)
{
    int idx = blockIdx.x * blockDim.x + threadIdx.x;
    if (idx >= B_ * 256 * 256) return;
    int x = idx & 255, y = (idx >> 8) & 255, b = idx >> 16;
    float v = g_mm[b * (N_ - 1) + (y >> 4) * 16 + (x >> 4)];
    if (y >= 8 && y < 248 && x >= 8 && x < 248) {
        float sh = g_mm[b * (N_ - 1) + 256 + ((y - 8) >> 4) * 15 + ((x - 8) >> 4)];
        v = 0.5f * (v + sh);
    }
    outp[idx] = v;
}

// ---------------- launch ----------------
extern "C" void kernel_launch(void* const* d_in, const int* in_sizes, int n_in,
                              void* d_out, int out_size)
{
    const float* x    = (const float*)d_in[0];
    const float* mask = (const float*)d_in[1];
    const float* Wqkv = (const float*)d_in[2];
    const float* Wout = (const float*)d_in[3];
    const float* bout = (const float*)d_in[4];
    float* out = (float*)d_out;

    float *p_qkv, *p_qkvm, *p_out2, *p_m2, *p_qq, *p_kk, *p_dots;
    cudaGetSymbolAddress((void**)&p_qkv,  g_qkv);
    cudaGetSymbolAddress((void**)&p_qkvm, g_qkvm);
    cudaGetSymbolAddress((void**)&p_out2, g_out2);
    cudaGetSymbolAddress((void**)&p_m2,   g_m2);
    cudaGetSymbolAddress((void**)&p_qq,   g_qq);
    cudaGetSymbolAddress((void**)&p_kk,   g_kk);
    cudaGetSymbolAddress((void**)&p_dots, g_dots);

    // 1-2. qkv = x @ Wqkv^T ; qkv_m = mask @ |Wqkv|^T   (tf32x3)
    mma_gemm<false,false,false><<<dim3(QKV_/128, BN_/128), 256>>>(x,    Wqkv, nullptr, p_qkv,
        BN_, QKV_, DIM_, DIM_, DIM_, QKV_, 0, 0, 0);
    mma_gemm<true, false,false><<<dim3(QKV_/128, BN_/128), 256>>>(mask, Wqkv, nullptr, p_qkvm,
        BN_, QKV_, DIM_, DIM_, DIM_, QKV_, 0, 0, 0);
    // 3. updated flags
    updated_k<<<(BN_ + 7) / 8, 256>>>(mask);
    // 4. maxima
    reduce_max_k<<<(B_*H_*3*D_ + 255) / 256, 256>>>();
    // 5. modulate
    modulate_k<<<(SZ_BND + 255) / 256, 256>>>();
    // 6. dots = qq @ kk^T  (batched tf32x3, bounded, ldc = LDP_)
    mma_gemm<false,false,true><<<dim3(4, 4, BH_), 256>>>(p_qq, p_kk, nullptr, p_dots,
        N_, N_, D_, D_, D_, LDP_, (long long)N_*D_, (long long)N_*D_, (long long)N_*LDP_);
    // 7. softmax
    softmax_rows<<<BH_ * N_, 128>>>();
    // 8. PV (both outputs)
    attn_pv_mma<<<dim3(4, BH_), 256>>>();
    // 9. blending
    blend_k<<<(SZ_BND + 255) / 256, 256>>>();
    // 10. channel means
    mm_k<<<(B_ * (N_ - 1) + 7) / 8, 256>>>();
    // 11. inter
    inter_k<<<(B_ * 65536 + 255) / 256, 256>>>(out + 2 * (size_t)SZ_BND);
    // 12-13. final projections (tf32x3) straight into d_out
    mma_gemm<false,true ,false><<<dim3(DIM_/128, BN_/128), 256>>>(p_out2, Wout, bout, out,
        BN_, DIM_, DIM_, DIM_, DIM_, DIM_, 0, 0, 0);
    mma_gemm<true, false,false><<<dim3(DIM_/128, BN_/128), 256>>>(p_m2,   Wout, nullptr, out + (size_t)SZ_BND,
        BN_, DIM_, DIM_, DIM_, DIM_, DIM_, 0, 0, 0);
}

// round 5
// speedup vs baseline: 2.4445x; 1.9990x over previous
#include <cuda_runtime.h>
#include <cstdint>

// ---------------- problem constants ----------------
#define B_    64
#define N_    482
#define DIM_  512
#define H_    8
#define D_    64
#define QKV_  1536
#define BH_   (B_*H_)          // 512
#define BN_   (B_*N_)          // 30848  (== 241*128)
#define SZ_BND (BN_*DIM_)      // 15794176
#define NHW_  256
#define NB_   225
#define TAIL0_ 257             // N_ - NB_
#define SCALE_ 0.125f
#define LDP_  512              // padded leading dim for dots (16B alignment)

// ---------------- device scratch ----------------
__device__ float g_qkv [(size_t)BN_*QKV_];
__device__ float g_qkvm[(size_t)BN_*QKV_];
__device__ float g_qq  [(size_t)BH_*N_*D_];
__device__ float g_kk  [(size_t)BH_*N_*D_];
__device__ float g_vv  [(size_t)BH_*N_*D_];
__device__ float g_vm  [(size_t)BH_*N_*D_];
__device__ float g_dots[(size_t)BH_*N_*LDP_];
__device__ float g_out [SZ_BND];
__device__ float g_m   [SZ_BND];
__device__ float g_out2[SZ_BND];
__device__ float g_m2  [SZ_BND];
__device__ float g_max [B_*H_*3*D_];
__device__ float g_upd [BN_];
__device__ float g_mm  [B_*(N_-1)];

// ---------------- tf32 mma helpers ----------------
__device__ __forceinline__ void mma_tf32(float* c, const uint32_t* a, const uint32_t* b) {
    asm volatile("mma.sync.aligned.m16n8k8.row.col.f32.tf32.tf32.f32 "
        "{%0,%1,%2,%3}, {%4,%5,%6,%7}, {%8,%9}, {%0,%1,%2,%3};"
        : "+f"(c[0]), "+f"(c[1]), "+f"(c[2]), "+f"(c[3])
        : "r"(a[0]), "r"(a[1]), "r"(a[2]), "r"(a[3]), "r"(b[0]), "r"(b[1]));
}
__device__ __forceinline__ uint32_t to_tf32(float x) {
    uint32_t h;
    asm("cvt.rna.tf32.f32 %0, %1;" : "=r"(h) : "f"(x));
    return h;
}
__device__ __forceinline__ uint4 to_tf32_v4(float4 v) {
    uint4 r;
    r.x = to_tf32(v.x); r.y = to_tf32(v.y); r.z = to_tf32(v.z); r.w = to_tf32(v.w);
    return r;
}

// ================= generic single-pass tf32 NT GEMM, 128x128 tile =================
// C[m,n] = sum_k A[m*lda+k] * f(B[n*ldb+k]) (+bias[n]); batched via blockIdx.z
// smem holds pre-converted tf32 bit patterns; inner loop = pure LDS + MMA.
template<bool ABS_B, bool BIAS, bool BOUND>
__global__ void __launch_bounds__(256) mma_gemm(const float* __restrict__ A,
                                                const float* __restrict__ Bm,
                                                const float* __restrict__ bias,
                                                float* __restrict__ C,
                                                int M, int N, int K,
                                                int lda, int ldb, int ldc,
                                                long long sA, long long sB, long long sC)
{
    __shared__ uint32_t As[128][36];
    __shared__ uint32_t Bs[128][36];
    A  += (long long)blockIdx.z * sA;
    Bm += (long long)blockIdx.z * sB;
    C  += (long long)blockIdx.z * sC;
    const int tid = threadIdx.x;
    const int bm = blockIdx.y * 128, bn = blockIdx.x * 128;
    const int lane = tid & 31, wid = tid >> 5;
    const int gr = lane >> 2, gc = lane & 3;
    const int wm = (wid & 1) * 64, wn = (wid >> 1) * 32;
    const int lr = tid >> 3, lc = (tid & 7) * 4;

    float acc[4][4][4];
    #pragma unroll
    for (int i = 0; i < 4; i++)
        #pragma unroll
        for (int j = 0; j < 4; j++)
            #pragma unroll
            for (int e = 0; e < 4; e++) acc[i][j][e] = 0.f;

    for (int kt = 0; kt < K; kt += 32) {
        #pragma unroll
        for (int r = 0; r < 4; r++) {
            int row = lr + r * 32;
            float4 av = make_float4(0.f,0.f,0.f,0.f);
            float4 bv = make_float4(0.f,0.f,0.f,0.f);
            if (!BOUND || bm + row < M) av = *(const float4*)(A  + (size_t)(bm + row) * lda + kt + lc);
            if (!BOUND || bn + row < N) bv = *(const float4*)(Bm + (size_t)(bn + row) * ldb + kt + lc);
            if (ABS_B) { bv.x = fabsf(bv.x); bv.y = fabsf(bv.y); bv.z = fabsf(bv.z); bv.w = fabsf(bv.w); }
            *(uint4*)&As[row][lc] = to_tf32_v4(av);
            *(uint4*)&Bs[row][lc] = to_tf32_v4(bv);
        }
        __syncthreads();
        #pragma unroll
        for (int ks = 0; ks < 4; ks++) {
            const int k0 = ks * 8;
            uint32_t ah[4][4], bh[4][2];
            #pragma unroll
            for (int mt = 0; mt < 4; mt++) {
                int r0 = wm + mt * 16 + gr;
                ah[mt][0] = As[r0    ][k0 + gc    ];
                ah[mt][1] = As[r0 + 8][k0 + gc    ];
                ah[mt][2] = As[r0    ][k0 + gc + 4];
                ah[mt][3] = As[r0 + 8][k0 + gc + 4];
            }
            #pragma unroll
            for (int nt = 0; nt < 4; nt++) {
                int c0 = wn + nt * 8 + gr;
                bh[nt][0] = Bs[c0][k0 + gc    ];
                bh[nt][1] = Bs[c0][k0 + gc + 4];
            }
            #pragma unroll
            for (int mt = 0; mt < 4; mt++)
                #pragma unroll
                for (int nt = 0; nt < 4; nt++)
                    mma_tf32(acc[mt][nt], ah[mt], bh[nt]);
        }
        __syncthreads();
    }
    #pragma unroll
    for (int mt = 0; mt < 4; mt++)
        #pragma unroll
        for (int nt = 0; nt < 4; nt++) {
            int m0 = bm + wm + mt * 16 + gr;
            int n0 = bn + wn + nt * 8 + gc * 2;
            float bx = 0.f, by = 0.f;
            if (BIAS) { bx = bias[n0]; by = bias[n0 + 1]; }
            if ((!BOUND || (m0 < M && n0 < N)))
                *(float2*)&C[(size_t)m0 * ldc + n0] = make_float2(acc[mt][nt][0] + bx, acc[mt][nt][1] + by);
            if ((!BOUND || (m0 + 8 < M && n0 < N)))
                *(float2*)&C[(size_t)(m0 + 8) * ldc + n0] = make_float2(acc[mt][nt][2] + bx, acc[mt][nt][3] + by);
        }
}

// ================= PV single-pass tf32: out = P@(v*vm), m = P@vm =================
__global__ void __launch_bounds__(256) attn_pv_mma()
{
    const int bh = blockIdx.y;
    const int b = bh >> 3, h = bh & 7;
    const int i0 = blockIdx.x * 128;
    const float* P  = g_dots + (size_t)bh * N_ * LDP_;
    const float* Vv = g_vv   + (size_t)bh * N_ * D_;
    const float* Vm = g_vm   + (size_t)bh * N_ * D_;
    __shared__ uint32_t Ps[128][36];
    __shared__ uint32_t V1[32][72];
    __shared__ uint32_t V2[32][72];
    const int tid = threadIdx.x;
    const int lane = tid & 31, wid = tid >> 5;
    const int gr = lane >> 2, gc = lane & 3;
    const int wm = (wid >> 1) * 32, wn = (wid & 1) * 32;

    float acc1[2][4][4], acc2[2][4][4];
    #pragma unroll
    for (int i = 0; i < 2; i++)
        #pragma unroll
        for (int j = 0; j < 4; j++)
            #pragma unroll
            for (int e = 0; e < 4; e++) { acc1[i][j][e] = 0.f; acc2[i][j][e] = 0.f; }

    for (int j0 = 0; j0 < N_; j0 += 32) {
        {   // P tile: 128 x 32  (ld = LDP_, 16B aligned)
            int lr = tid >> 3, lc = (tid & 7) * 4;
            #pragma unroll
            for (int r = 0; r < 4; r++) {
                int row = lr + r * 32;
                float4 pv = make_float4(0.f,0.f,0.f,0.f);
                if (i0 + row < N_) {
                    pv = *(const float4*)(P + (size_t)(i0 + row) * LDP_ + j0 + lc);
                    if (j0 + lc + 3 >= N_) {
                        if (j0 + lc + 0 >= N_) pv.x = 0.f;
                        if (j0 + lc + 1 >= N_) pv.y = 0.f;
                        if (j0 + lc + 2 >= N_) pv.z = 0.f;
                        if (j0 + lc + 3 >= N_) pv.w = 0.f;
                    }
                }
                *(uint4*)&Ps[row][lc] = to_tf32_v4(pv);
            }
        }
        {   // V tiles: 32 x 64
            int r = tid >> 4, c = (tid & 15) * 4;
            #pragma unroll
            for (int e = 0; e < 2; e++) {
                int row = r + e * 16;
                float4 v1 = make_float4(0.f,0.f,0.f,0.f);
                float4 v2 = make_float4(0.f,0.f,0.f,0.f);
                if (j0 + row < N_) {
                    v1 = *(const float4*)(Vv + (size_t)(j0 + row) * D_ + c);
                    v2 = *(const float4*)(Vm + (size_t)(j0 + row) * D_ + c);
                }
                *(uint4*)&V1[row][c] = to_tf32_v4(v1);
                *(uint4*)&V2[row][c] = to_tf32_v4(v2);
            }
        }
        __syncthreads();
        #pragma unroll
        for (int ks = 0; ks < 4; ks++) {
            const int k0 = ks * 8;
            uint32_t ah[2][4];
            #pragma unroll
            for (int mt = 0; mt < 2; mt++) {
                int r0 = wm + mt * 16 + gr;
                ah[mt][0] = Ps[r0    ][k0 + gc    ];
                ah[mt][1] = Ps[r0 + 8][k0 + gc    ];
                ah[mt][2] = Ps[r0    ][k0 + gc + 4];
                ah[mt][3] = Ps[r0 + 8][k0 + gc + 4];
            }
            #pragma unroll
            for (int nt = 0; nt < 4; nt++) {
                int c0 = wn + nt * 8 + gr;
                uint32_t bv1[2], bv2[2];
                bv1[0] = V1[k0 + gc    ][c0];
                bv1[1] = V1[k0 + gc + 4][c0];
                bv2[0] = V2[k0 + gc    ][c0];
                bv2[1] = V2[k0 + gc + 4][c0];
                #pragma unroll
                for (int mt = 0; mt < 2; mt++) {
                    mma_tf32(acc1[mt][nt], ah[mt], bv1);
                    mma_tf32(acc2[mt][nt], ah[mt], bv2);
                }
            }
        }
        __syncthreads();
    }
    #pragma unroll
    for (int mt = 0; mt < 2; mt++)
        #pragma unroll
        for (int nt = 0; nt < 4; nt++) {
            int d = wn + nt * 8 + gc * 2;
            #pragma unroll
            for (int half = 0; half < 2; half++) {
                int gi = i0 + wm + mt * 16 + gr + half * 8;
                if (gi < N_) {
                    float u = g_upd[b * N_ + gi];
                    size_t base = (size_t)(b * N_ + gi) * DIM_ + h * 64 + d;
                    *(float2*)&g_out[base] = make_float2(acc1[mt][nt][half*2]*u, acc1[mt][nt][half*2+1]*u);
                    *(float2*)&g_m  [base] = make_float2(acc2[mt][nt][half*2]*u, acc2[mt][nt][half*2+1]*u);
                }
            }
        }
}

// ---------------- updated[b,i] ----------------
__global__ void updated_k(const float* __restrict__ mask)
{
    int row = blockIdx.x * (blockDim.x >> 5) + (threadIdx.x >> 5);
    if (row >= BN_) return;
    int ln = threadIdx.x & 31;
    const float* p = mask + (size_t)row * DIM_;
    float s = 0.f;
    #pragma unroll
    for (int e = ln; e < DIM_; e += 32) s += p[e];
    #pragma unroll
    for (int o = 16; o > 0; o >>= 1) s += __shfl_xor_sync(0xffffffffu, s, o);
    if (ln == 0) {
        int i = row % N_;
        g_upd[row] = (i == 0) ? 1.0f : (s > 0.0f ? 1.0f : 0.0f);
    }
}

// ---------------- per-(b,h,w,d) max over sequence ----------------
__global__ void reduce_max_k()
{
    int o = blockIdx.x * blockDim.x + threadIdx.x;
    if (o >= B_*H_*3*D_) return;
    int d = o & 63;
    int w = (o >> 6) % 3;
    int h = ((o >> 6) / 3) % H_;
    int b = (o >> 6) / 24;
    const float* p = g_qkvm + (size_t)b * N_ * QKV_ + w * DIM_ + h * 64 + d;
    float mx = -1e30f;
    for (int i = 0; i < N_; i++) mx = fmaxf(mx, p[(size_t)i * QKV_]);
    g_max[o] = mx;
}

// ---------------- modulated q,k,v ----------------
__global__ void modulate_k()
{
    int idx = blockIdx.x * blockDim.x + threadIdx.x;
    if (idx >= SZ_BND) return;
    int hd = idx % DIM_;
    int i  = (idx / DIM_) % N_;
    int b  = idx / (DIM_ * N_);
    int h = hd >> 6, d = hd & 63;
    size_t base = (size_t)(b * N_ + i) * QKV_;
    float q  = g_qkv [base + hd];
    float k  = g_qkv [base + DIM_ + hd];
    float v  = g_qkv [base + 2*DIM_ + hd];
    float qm = g_qkvm[base + hd];
    float km = g_qkvm[base + DIM_ + hd];
    float vm = g_qkvm[base + 2*DIM_ + hd];
    int mb = ((b * H_ + h) * 3) * 64 + d;
    float qmn = qm / (1e-6f + g_max[mb]);
    float kmn = km / (1e-6f + g_max[mb + 64]);
    float vmn = vm / (1e-6f + g_max[mb + 128]);
    size_t o = ((size_t)(b * H_ + h) * N_ + i) * D_ + d;
    g_qq[o] = q * qmn * SCALE_;
    g_kk[o] = k * kmn;
    g_vv[o] = v * vmn;
    g_vm[o] = vmn;
}

// ---------------- softmax (stride LDP_) ----------------
__global__ void __launch_bounds__(128) softmax_rows()
{
    size_t row = blockIdx.x;
    float* p = g_dots + row * LDP_;
    int tid = threadIdx.x;
    float v[4];
    float mx = -1e30f;
    #pragma unroll
    for (int e = 0; e < 4; e++) {
        int j = tid + e * 128;
        if (j < N_) { v[e] = p[j]; mx = fmaxf(mx, v[e]); } else v[e] = -1e30f;
    }
    #pragma unroll
    for (int o = 16; o > 0; o >>= 1) mx = fmaxf(mx, __shfl_xor_sync(0xffffffffu, mx, o));
    __shared__ float smax[4], ssum[4];
    int w = tid >> 5, ln = tid & 31;
    if (ln == 0) smax[w] = mx;
    __syncthreads();
    mx = fmaxf(fmaxf(smax[0], smax[1]), fmaxf(smax[2], smax[3]));
    float sum = 0.f;
    #pragma unroll
    for (int e = 0; e < 4; e++) {
        int j = tid + e * 128;
        if (j < N_) { v[e] = __expf(v[e] - mx); sum += v[e]; }
    }
    #pragma unroll
    for (int o = 16; o > 0; o >>= 1) sum += __shfl_xor_sync(0xffffffffu, sum, o);
    if (ln == 0) ssum[w] = sum;
    __syncthreads();
    float inv = 1.0f / (ssum[0] + ssum[1] + ssum[2] + ssum[3]);
    #pragma unroll
    for (int e = 0; e < 4; e++) {
        int j = tid + e * 128;
        if (j < N_) p[j] = v[e] * inv;
    }
}

// ---------------- overlap blending ----------------
__global__ void blend_k()
{
    int idx = blockIdx.x * blockDim.x + threadIdx.x;
    if (idx >= SZ_BND) return;
    int c = idx % DIM_;
    int i = (idx / DIM_) % N_;
    int b = idx / (DIM_ * N_);
    float o = g_out[idx], mv = g_m[idx];
    if (i >= 1 && i <= NHW_) {
        int p = i - 1, y = p >> 4, x = p & 15;
        float inv = 1.0f - g_upd[b * N_ + i];
        float s1 = 0.f, s2 = 0.f;
        #pragma unroll
        for (int dy = -1; dy <= 0; dy++)
            #pragma unroll
            for (int dx = -1; dx <= 0; dx++) {
                int r = y + dy, cc = x + dx;
                if (r >= 0 && r < 15 && cc >= 0 && cc < 15) {
                    size_t src = ((size_t)(b * N_ + TAIL0_ + r * 15 + cc)) * DIM_ + c;
                    s1 += g_out[src]; s2 += g_m[src];
                }
            }
        o  += 0.25f * s1 * inv;
        mv += 0.25f * s2 * inv;
    } else if (i >= TAIL0_) {
        int p = i - TAIL0_, r = p / 15, cc = p % 15;
        float inv = 1.0f - g_upd[b * N_ + i];
        float s1 = 0.f, s2 = 0.f;
        #pragma unroll
        for (int dy = 0; dy <= 1; dy++)
            #pragma unroll
            for (int dx = 0; dx <= 1; dx++) {
                size_t src = ((size_t)(b * N_ + 1 + (r + dy) * 16 + (cc + dx))) * DIM_ + c;
                s1 += g_out[src]; s2 += g_m[src];
            }
        o  += 0.25f * s1 * inv;
        mv += 0.25f * s2 * inv;
    }
    g_out2[idx] = o;
    g_m2[idx] = mv;
}

// ---------------- channel means ----------------
__global__ void mm_k()
{
    int row = blockIdx.x * (blockDim.x >> 5) + (threadIdx.x >> 5);
    if (row >= B_ * (N_ - 1)) return;
    int b = row / (N_ - 1), j = row % (N_ - 1);
    int ln = threadIdx.x & 31;
    const float* p = g_m2 + (size_t)(b * N_ + j + 1) * DIM_;
    float s = 0.f;
    #pragma unroll
    for (int e = ln; e < DIM_; e += 32) s += p[e];
    #pragma unroll
    for (int o = 16; o > 0; o >>= 1) s += __shfl_xor_sync(0xffffffffu, s, o);
    if (ln == 0) g_mm[row] = s * (1.0f / DIM_);
}

// ---------------- inter ----------------
__global__ void inter_k(float* __restrict__ outp)
{
    int idx = blockIdx.x * blockDim.x + threadIdx.x;
    if (idx >= B_ * 256 * 256) return;
    int x = idx & 255, y = (idx >> 8) & 255, b = idx >> 16;
    float v = g_mm[b * (N_ - 1) + (y >> 4) * 16 + (x >> 4)];
    if (y >= 8 && y < 248 && x >= 8 && x < 248) {
        float sh = g_mm[b * (N_ - 1) + 256 + ((y - 8) >> 4) * 15 + ((x - 8) >> 4)];
        v = 0.5f * (v + sh);
    }
    outp[idx] = v;
}

// ---------------- launch ----------------
extern "C" void kernel_launch(void* const* d_in, const int* in_sizes, int n_in,
                              void* d_out, int out_size)
{
    const float* x    = (const float*)d_in[0];
    const float* mask = (const float*)d_in[1];
    const float* Wqkv = (const float*)d_in[2];
    const float* Wout = (const float*)d_in[3];
    const float* bout = (const float*)d_in[4];
    float* out = (float*)d_out;

    float *p_qkv, *p_qkvm, *p_out2, *p_m2, *p_qq, *p_kk, *p_dots;
    cudaGetSymbolAddress((void**)&p_qkv,  g_qkv);
    cudaGetSymbolAddress((void**)&p_qkvm, g_qkvm);
    cudaGetSymbolAddress((void**)&p_out2, g_out2);
    cudaGetSymbolAddress((void**)&p_m2,   g_m2);
    cudaGetSymbolAddress((void**)&p_qq,   g_qq);
    cudaGetSymbolAddress((void**)&p_kk,   g_kk);
    cudaGetSymbolAddress((void**)&p_dots, g_dots);

    // 1-2. qkv = x @ Wqkv^T ; qkv_m = mask @ |Wqkv|^T   (tf32)
    mma_gemm<false,false,false><<<dim3(QKV_/128, BN_/128), 256>>>(x,    Wqkv, nullptr, p_qkv,
        BN_, QKV_, DIM_, DIM_, DIM_, QKV_, 0, 0, 0);
    mma_gemm<true, false,false><<<dim3(QKV_/128, BN_/128), 256>>>(mask, Wqkv, nullptr, p_qkvm,
        BN_, QKV_, DIM_, DIM_, DIM_, QKV_, 0, 0, 0);
    // 3. updated flags
    updated_k<<<(BN_ + 7) / 8, 256>>>(mask);
    // 4. maxima
    reduce_max_k<<<(B_*H_*3*D_ + 255) / 256, 256>>>();
    // 5. modulate
    modulate_k<<<(SZ_BND + 255) / 256, 256>>>();
    // 6. dots = qq @ kk^T  (batched tf32, bounded, ldc = LDP_)
    mma_gemm<false,false,true><<<dim3(4, 4, BH_), 256>>>(p_qq, p_kk, nullptr, p_dots,
        N_, N_, D_, D_, D_, LDP_, (long long)N_*D_, (long long)N_*D_, (long long)N_*LDP_);
    // 7. softmax
    softmax_rows<<<BH_ * N_, 128>>>();
    // 8. PV (both outputs)
    attn_pv_mma<<<dim3(4, BH_), 256>>>();
    // 9. blending
    blend_k<<<(SZ_BND + 255) / 256, 256>>>();
    // 10. channel means
    mm_k<<<(B_ * (N_ - 1) + 7) / 8, 256>>>();
    // 11. inter
    inter_k<<<(B_ * 65536 + 255) / 256, 256>>>(out + 2 * (size_t)SZ_BND);
    // 12-13. final projections (tf32) straight into d_out
    mma_gemm<false,true ,false><<<dim3(DIM_/128, BN_/128), 256>>>(p_out2, Wout, bout, out,
        BN_, DIM_, DIM_, DIM_, DIM_, DIM_, 0, 0, 0);
    mma_gemm<true, false,false><<<dim3(DIM_/128, BN_/128), 256>>>(p_m2,   Wout, nullptr, out + (size_t)SZ_BND,
        BN_, DIM_, DIM_, DIM_, DIM_, DIM_, 0, 0, 0);
}

// round 6
// speedup vs baseline: 3.0493x; 1.2474x over previous
#include <cuda_runtime.h>
#include <cstdint>

// ---------------- problem constants ----------------
#define B_    64
#define N_    482
#define DIM_  512
#define H_    8
#define D_    64
#define QKV_  1536
#define BH_   (B_*H_)          // 512
#define BN_   (B_*N_)          // 30848
#define SZ_BND (BN_*DIM_)      // 15794176
#define NHW_  256
#define NB_   225
#define TAIL0_ 257
#define SCALE_ 0.125f

// ---------------- device scratch ----------------
__device__ float g_qkv [(size_t)BN_*QKV_];
__device__ float g_qkvm[(size_t)BN_*QKV_];
__device__ float g_qq  [(size_t)BH_*N_*D_];
__device__ float g_kk  [(size_t)BH_*N_*D_];
__device__ float g_vv  [(size_t)BH_*N_*D_];
__device__ float g_vm  [(size_t)BH_*N_*D_];
__device__ float g_out [SZ_BND];
__device__ float g_m   [SZ_BND];
__device__ float g_out2[SZ_BND];
__device__ float g_m2  [SZ_BND];
__device__ float g_max [B_*H_*3*D_];
__device__ float g_upd [BN_];
__device__ float g_mm  [B_*(N_-1)];

// ---------------- tf32 mma helpers ----------------
__device__ __forceinline__ void mma_tf32(float* c, const uint32_t* a, const uint32_t* b) {
    asm volatile("mma.sync.aligned.m16n8k8.row.col.f32.tf32.tf32.f32 "
        "{%0,%1,%2,%3}, {%4,%5,%6,%7}, {%8,%9}, {%0,%1,%2,%3};"
        : "+f"(c[0]), "+f"(c[1]), "+f"(c[2]), "+f"(c[3])
        : "r"(a[0]), "r"(a[1]), "r"(a[2]), "r"(a[3]), "r"(b[0]), "r"(b[1]));
}
__device__ __forceinline__ uint32_t to_tf32(float x) {
    uint32_t h;
    asm("cvt.rna.tf32.f32 %0, %1;" : "=r"(h) : "f"(x));
    return h;
}
__device__ __forceinline__ uint4 to_tf32_v4(float4 v) {
    uint4 r;
    r.x = to_tf32(v.x); r.y = to_tf32(v.y); r.z = to_tf32(v.z); r.w = to_tf32(v.w);
    return r;
}

// ================= generic single-pass tf32 NT GEMM, 128x128 tile =================
template<bool ABS_B, bool BIAS, bool BOUND>
__global__ void __launch_bounds__(256) mma_gemm(const float* __restrict__ A,
                                                const float* __restrict__ Bm,
                                                const float* __restrict__ bias,
                                                float* __restrict__ C,
                                                int M, int N, int K,
                                                int lda, int ldb, int ldc,
                                                long long sA, long long sB, long long sC)
{
    __shared__ uint32_t As[128][36];
    __shared__ uint32_t Bs[128][36];
    A  += (long long)blockIdx.z * sA;
    Bm += (long long)blockIdx.z * sB;
    C  += (long long)blockIdx.z * sC;
    const int tid = threadIdx.x;
    const int bm = blockIdx.y * 128, bn = blockIdx.x * 128;
    const int lane = tid & 31, wid = tid >> 5;
    const int gr = lane >> 2, gc = lane & 3;
    const int wm = (wid & 1) * 64, wn = (wid >> 1) * 32;
    const int lr = tid >> 3, lc = (tid & 7) * 4;

    float acc[4][4][4];
    #pragma unroll
    for (int i = 0; i < 4; i++)
        #pragma unroll
        for (int j = 0; j < 4; j++)
            #pragma unroll
            for (int e = 0; e < 4; e++) acc[i][j][e] = 0.f;

    for (int kt = 0; kt < K; kt += 32) {
        #pragma unroll
        for (int r = 0; r < 4; r++) {
            int row = lr + r * 32;
            float4 av = make_float4(0.f,0.f,0.f,0.f);
            float4 bv = make_float4(0.f,0.f,0.f,0.f);
            if (!BOUND || bm + row < M) av = *(const float4*)(A  + (size_t)(bm + row) * lda + kt + lc);
            if (!BOUND || bn + row < N) bv = *(const float4*)(Bm + (size_t)(bn + row) * ldb + kt + lc);
            if (ABS_B) { bv.x = fabsf(bv.x); bv.y = fabsf(bv.y); bv.z = fabsf(bv.z); bv.w = fabsf(bv.w); }
            *(uint4*)&As[row][lc] = to_tf32_v4(av);
            *(uint4*)&Bs[row][lc] = to_tf32_v4(bv);
        }
        __syncthreads();
        #pragma unroll
        for (int ks = 0; ks < 4; ks++) {
            const int k0 = ks * 8;
            uint32_t ah[4][4], bh[4][2];
            #pragma unroll
            for (int mt = 0; mt < 4; mt++) {
                int r0 = wm + mt * 16 + gr;
                ah[mt][0] = As[r0    ][k0 + gc    ];
                ah[mt][1] = As[r0 + 8][k0 + gc    ];
                ah[mt][2] = As[r0    ][k0 + gc + 4];
                ah[mt][3] = As[r0 + 8][k0 + gc + 4];
            }
            #pragma unroll
            for (int nt = 0; nt < 4; nt++) {
                int c0 = wn + nt * 8 + gr;
                bh[nt][0] = Bs[c0][k0 + gc    ];
                bh[nt][1] = Bs[c0][k0 + gc + 4];
            }
            #pragma unroll
            for (int mt = 0; mt < 4; mt++)
                #pragma unroll
                for (int nt = 0; nt < 4; nt++)
                    mma_tf32(acc[mt][nt], ah[mt], bh[nt]);
        }
        __syncthreads();
    }
    #pragma unroll
    for (int mt = 0; mt < 4; mt++)
        #pragma unroll
        for (int nt = 0; nt < 4; nt++) {
            int m0 = bm + wm + mt * 16 + gr;
            int n0 = bn + wn + nt * 8 + gc * 2;
            float bx = 0.f, by = 0.f;
            if (BIAS) { bx = bias[n0]; by = bias[n0 + 1]; }
            if ((!BOUND || (m0 < M && n0 < N)))
                *(float2*)&C[(size_t)m0 * ldc + n0] = make_float2(acc[mt][nt][0] + bx, acc[mt][nt][1] + by);
            if ((!BOUND || (m0 + 8 < M && n0 < N)))
                *(float2*)&C[(size_t)(m0 + 8) * ldc + n0] = make_float2(acc[mt][nt][2] + bx, acc[mt][nt][3] + by);
        }
}

// ================= flash attention: fused QK^T + online softmax + dual PV =======
// grid (4, BH_), 256 threads, 1 warp owns 16 consecutive rows of the 128-row i-tile.
// smem (dynamic): Kt[64][68] | V1[64][72] | V2[64][72] | PQ[128][68] (Q staging / P tiles)
#define KT_OFF  0
#define V1_OFF  (64*68)
#define V2_OFF  (V1_OFF + 64*72)
#define PQ_OFF  (V2_OFF + 64*72)
#define FA_SMEM_WORDS (PQ_OFF + 128*68)
extern __shared__ uint32_t s_fa[];

__global__ void __launch_bounds__(256, 1) flash_attn()
{
    const int bh = blockIdx.y;
    const int b = bh >> 3, h = bh & 7;
    const int i0 = blockIdx.x * 128;
    const float* Q  = g_qq + (size_t)bh * N_ * D_;
    const float* Kp = g_kk + (size_t)bh * N_ * D_;
    const float* Vv = g_vv + (size_t)bh * N_ * D_;
    const float* Vm = g_vm + (size_t)bh * N_ * D_;
    uint32_t* Kt = s_fa + KT_OFF;
    uint32_t* V1 = s_fa + V1_OFF;
    uint32_t* V2 = s_fa + V2_OFF;
    uint32_t* PQ = s_fa + PQ_OFF;

    const int tid = threadIdx.x;
    const int lane = tid & 31, wid = tid >> 5;
    const int gr = lane >> 2, gc = lane & 3;
    const int rbase = wid * 16;

    // ---- stage Q (coalesced) then pull frags to registers ----
    {
        float* Qst = (float*)PQ;
        int c = (tid & 15) * 4, r = tid >> 4;
        #pragma unroll
        for (int e = 0; e < 8; e++) {
            int row = r + e * 16, gi = i0 + row;
            float4 q = make_float4(0.f,0.f,0.f,0.f);
            if (gi < N_) q = *(const float4*)(Q + (size_t)gi * D_ + c);
            *(float4*)&Qst[row * 68 + c] = q;
        }
    }
    __syncthreads();
    uint32_t qf[8][4];
    {
        const float* Qst = (const float*)PQ;
        #pragma unroll
        for (int kc = 0; kc < 8; kc++) {
            qf[kc][0] = to_tf32(Qst[(rbase + gr    ) * 68 + kc*8 + gc    ]);
            qf[kc][1] = to_tf32(Qst[(rbase + gr + 8) * 68 + kc*8 + gc    ]);
            qf[kc][2] = to_tf32(Qst[(rbase + gr    ) * 68 + kc*8 + gc + 4]);
            qf[kc][3] = to_tf32(Qst[(rbase + gr + 8) * 68 + kc*8 + gc + 4]);
        }
    }
    __syncthreads();

    float acc1[8][4], acc2[8][4];
    #pragma unroll
    for (int nt = 0; nt < 8; nt++)
        #pragma unroll
        for (int e = 0; e < 4; e++) { acc1[nt][e] = 0.f; acc2[nt][e] = 0.f; }
    float rmax0 = -1e30f, rmax1 = -1e30f, rsum0 = 0.f, rsum1 = 0.f;

    for (int j0 = 0; j0 < N_; j0 += 64) {
        // ---- load K, V1, V2 tiles (tf32 in smem) ----
        {
            int c = (tid & 15) * 4, r = tid >> 4;
            #pragma unroll
            for (int e = 0; e < 4; e++) {
                int row = r + e * 16, j = j0 + row;
                float4 kv = make_float4(0.f,0.f,0.f,0.f);
                float4 v1 = kv, v2 = kv;
                if (j < N_) {
                    kv = *(const float4*)(Kp + (size_t)j * D_ + c);
                    v1 = *(const float4*)(Vv + (size_t)j * D_ + c);
                    v2 = *(const float4*)(Vm + (size_t)j * D_ + c);
                }
                *(uint4*)&Kt[row * 68 + c] = to_tf32_v4(kv);
                *(uint4*)&V1[row * 72 + c] = to_tf32_v4(v1);
                *(uint4*)&V2[row * 72 + c] = to_tf32_v4(v2);
            }
        }
        __syncthreads();

        // ---- S = Q @ K^T (m16 x n64 per warp) ----
        float sacc[8][4];
        #pragma unroll
        for (int nt = 0; nt < 8; nt++)
            #pragma unroll
            for (int e = 0; e < 4; e++) sacc[nt][e] = 0.f;
        #pragma unroll
        for (int nt = 0; nt < 8; nt++) {
            #pragma unroll
            for (int kc = 0; kc < 8; kc++) {
                uint32_t bf[2];
                bf[0] = Kt[(nt*8 + gr) * 68 + kc*8 + gc    ];
                bf[1] = Kt[(nt*8 + gr) * 68 + kc*8 + gc + 4];
                mma_tf32(sacc[nt], qf[kc], bf);
            }
        }
        // ---- mask tail columns ----
        if (j0 + 64 > N_) {
            #pragma unroll
            for (int nt = 0; nt < 8; nt++) {
                int cc = j0 + nt*8 + gc*2;
                if (cc     >= N_) { sacc[nt][0] = -1e30f; sacc[nt][2] = -1e30f; }
                if (cc + 1 >= N_) { sacc[nt][1] = -1e30f; sacc[nt][3] = -1e30f; }
            }
        }
        // ---- online softmax ----
        float tm0 = -1e30f, tm1 = -1e30f;
        #pragma unroll
        for (int nt = 0; nt < 8; nt++) {
            tm0 = fmaxf(tm0, fmaxf(sacc[nt][0], sacc[nt][1]));
            tm1 = fmaxf(tm1, fmaxf(sacc[nt][2], sacc[nt][3]));
        }
        tm0 = fmaxf(tm0, __shfl_xor_sync(0xffffffffu, tm0, 1));
        tm0 = fmaxf(tm0, __shfl_xor_sync(0xffffffffu, tm0, 2));
        tm1 = fmaxf(tm1, __shfl_xor_sync(0xffffffffu, tm1, 1));
        tm1 = fmaxf(tm1, __shfl_xor_sync(0xffffffffu, tm1, 2));
        float nm0 = fmaxf(rmax0, tm0), nm1 = fmaxf(rmax1, tm1);
        float sc0 = __expf(rmax0 - nm0), sc1 = __expf(rmax1 - nm1);
        rmax0 = nm0; rmax1 = nm1;
        float ps0 = 0.f, ps1 = 0.f;
        #pragma unroll
        for (int nt = 0; nt < 8; nt++) {
            float p00 = __expf(sacc[nt][0] - nm0);
            float p01 = __expf(sacc[nt][1] - nm0);
            float p10 = __expf(sacc[nt][2] - nm1);
            float p11 = __expf(sacc[nt][3] - nm1);
            ps0 += p00 + p01; ps1 += p10 + p11;
            uint2 w0 = make_uint2(to_tf32(p00), to_tf32(p01));
            uint2 w1 = make_uint2(to_tf32(p10), to_tf32(p11));
            *(uint2*)&PQ[(rbase + gr    ) * 68 + nt*8 + gc*2] = w0;
            *(uint2*)&PQ[(rbase + gr + 8) * 68 + nt*8 + gc*2] = w1;
            // rescale accumulators
            acc1[nt][0] *= sc0; acc1[nt][1] *= sc0; acc1[nt][2] *= sc1; acc1[nt][3] *= sc1;
            acc2[nt][0] *= sc0; acc2[nt][1] *= sc0; acc2[nt][2] *= sc1; acc2[nt][3] *= sc1;
        }
        ps0 += __shfl_xor_sync(0xffffffffu, ps0, 1);
        ps0 += __shfl_xor_sync(0xffffffffu, ps0, 2);
        ps1 += __shfl_xor_sync(0xffffffffu, ps1, 1);
        ps1 += __shfl_xor_sync(0xffffffffu, ps1, 2);
        rsum0 = rsum0 * sc0 + ps0;
        rsum1 = rsum1 * sc1 + ps1;
        __syncwarp();   // P frags visible within warp (warp reads only its own 16 rows)

        // ---- PV: acc1 += P@V1, acc2 += P@V2 ----
        #pragma unroll
        for (int kc = 0; kc < 8; kc++) {
            uint32_t af[4];
            af[0] = PQ[(rbase + gr    ) * 68 + kc*8 + gc    ];
            af[1] = PQ[(rbase + gr + 8) * 68 + kc*8 + gc    ];
            af[2] = PQ[(rbase + gr    ) * 68 + kc*8 + gc + 4];
            af[3] = PQ[(rbase + gr + 8) * 68 + kc*8 + gc + 4];
            #pragma unroll
            for (int nt = 0; nt < 8; nt++) {
                uint32_t bv1[2], bv2[2];
                bv1[0] = V1[(kc*8 + gc    ) * 72 + nt*8 + gr];
                bv1[1] = V1[(kc*8 + gc + 4) * 72 + nt*8 + gr];
                bv2[0] = V2[(kc*8 + gc    ) * 72 + nt*8 + gr];
                bv2[1] = V2[(kc*8 + gc + 4) * 72 + nt*8 + gr];
                mma_tf32(acc1[nt], af, bv1);
                mma_tf32(acc2[nt], af, bv2);
            }
        }
        __syncthreads();   // protect K/V1/V2 (+PQ) before next tile load
    }

    // ---- epilogue: normalize, *updated, write [B,n,512] ----
    float inv0 = 1.0f / rsum0, inv1 = 1.0f / rsum1;
    int gi0 = i0 + rbase + gr, gi1 = gi0 + 8;
    if (gi0 < N_) {
        float f = inv0 * g_upd[b * N_ + gi0];
        size_t base = (size_t)(b * N_ + gi0) * DIM_ + h * 64;
        #pragma unroll
        for (int nt = 0; nt < 8; nt++) {
            int d = nt*8 + gc*2;
            *(float2*)&g_out[base + d] = make_float2(acc1[nt][0]*f, acc1[nt][1]*f);
            *(float2*)&g_m  [base + d] = make_float2(acc2[nt][0]*f, acc2[nt][1]*f);
        }
    }
    if (gi1 < N_) {
        float f = inv1 * g_upd[b * N_ + gi1];
        size_t base = (size_t)(b * N_ + gi1) * DIM_ + h * 64;
        #pragma unroll
        for (int nt = 0; nt < 8; nt++) {
            int d = nt*8 + gc*2;
            *(float2*)&g_out[base + d] = make_float2(acc1[nt][2]*f, acc1[nt][3]*f);
            *(float2*)&g_m  [base + d] = make_float2(acc2[nt][2]*f, acc2[nt][3]*f);
        }
    }
}

// ---------------- updated[b,i] ----------------
__global__ void updated_k(const float* __restrict__ mask)
{
    int row = blockIdx.x * (blockDim.x >> 5) + (threadIdx.x >> 5);
    if (row >= BN_) return;
    int ln = threadIdx.x & 31;
    const float* p = mask + (size_t)row * DIM_;
    float s = 0.f;
    #pragma unroll
    for (int e = ln; e < DIM_; e += 32) s += p[e];
    #pragma unroll
    for (int o = 16; o > 0; o >>= 1) s += __shfl_xor_sync(0xffffffffu, s, o);
    if (ln == 0) {
        int i = row % N_;
        g_upd[row] = (i == 0) ? 1.0f : (s > 0.0f ? 1.0f : 0.0f);
    }
}

// ---------------- per-(b,h,w,d) max over sequence ----------------
__global__ void reduce_max_k()
{
    int o = blockIdx.x * blockDim.x + threadIdx.x;
    if (o >= B_*H_*3*D_) return;
    int d = o & 63;
    int w = (o >> 6) % 3;
    int h = ((o >> 6) / 3) % H_;
    int b = (o >> 6) / 24;
    const float* p = g_qkvm + (size_t)b * N_ * QKV_ + w * DIM_ + h * 64 + d;
    float mx = -1e30f;
    for (int i = 0; i < N_; i++) mx = fmaxf(mx, p[(size_t)i * QKV_]);
    g_max[o] = mx;
}

// ---------------- modulated q,k,v ----------------
__global__ void modulate_k()
{
    int idx = blockIdx.x * blockDim.x + threadIdx.x;
    if (idx >= SZ_BND) return;
    int hd = idx % DIM_;
    int i  = (idx / DIM_) % N_;
    int b  = idx / (DIM_ * N_);
    int h = hd >> 6, d = hd & 63;
    size_t base = (size_t)(b * N_ + i) * QKV_;
    float q  = g_qkv [base + hd];
    float k  = g_qkv [base + DIM_ + hd];
    float v  = g_qkv [base + 2*DIM_ + hd];
    float qm = g_qkvm[base + hd];
    float km = g_qkvm[base + DIM_ + hd];
    float vm = g_qkvm[base + 2*DIM_ + hd];
    int mb = ((b * H_ + h) * 3) * 64 + d;
    float qmn = qm / (1e-6f + g_max[mb]);
    float kmn = km / (1e-6f + g_max[mb + 64]);
    float vmn = vm / (1e-6f + g_max[mb + 128]);
    size_t o = ((size_t)(b * H_ + h) * N_ + i) * D_ + d;
    g_qq[o] = q * qmn * SCALE_;
    g_kk[o] = k * kmn;
    g_vv[o] = v * vmn;
    g_vm[o] = vmn;
}

// ---------------- overlap blending ----------------
__global__ void blend_k()
{
    int idx = blockIdx.x * blockDim.x + threadIdx.x;
    if (idx >= SZ_BND) return;
    int c = idx % DIM_;
    int i = (idx / DIM_) % N_;
    int b = idx / (DIM_ * N_);
    float o = g_out[idx], mv = g_m[idx];
    if (i >= 1 && i <= NHW_) {
        int p = i - 1, y = p >> 4, x = p & 15;
        float inv = 1.0f - g_upd[b * N_ + i];
        float s1 = 0.f, s2 = 0.f;
        #pragma unroll
        for (int dy = -1; dy <= 0; dy++)
            #pragma unroll
            for (int dx = -1; dx <= 0; dx++) {
                int r = y + dy, cc = x + dx;
                if (r >= 0 && r < 15 && cc >= 0 && cc < 15) {
                    size_t src = ((size_t)(b * N_ + TAIL0_ + r * 15 + cc)) * DIM_ + c;
                    s1 += g_out[src]; s2 += g_m[src];
                }
            }
        o  += 0.25f * s1 * inv;
        mv += 0.25f * s2 * inv;
    } else if (i >= TAIL0_) {
        int p = i - TAIL0_, r = p / 15, cc = p % 15;
        float inv = 1.0f - g_upd[b * N_ + i];
        float s1 = 0.f, s2 = 0.f;
        #pragma unroll
        for (int dy = 0; dy <= 1; dy++)
            #pragma unroll
            for (int dx = 0; dx <= 1; dx++) {
                size_t src = ((size_t)(b * N_ + 1 + (r + dy) * 16 + (cc + dx))) * DIM_ + c;
                s1 += g_out[src]; s2 += g_m[src];
            }
        o  += 0.25f * s1 * inv;
        mv += 0.25f * s2 * inv;
    }
    g_out2[idx] = o;
    g_m2[idx] = mv;
}

// ---------------- channel means ----------------
__global__ void mm_k()
{
    int row = blockIdx.x * (blockDim.x >> 5) + (threadIdx.x >> 5);
    if (row >= B_ * (N_ - 1)) return;
    int b = row / (N_ - 1), j = row % (N_ - 1);
    int ln = threadIdx.x & 31;
    const float* p = g_m2 + (size_t)(b * N_ + j + 1) * DIM_;
    float s = 0.f;
    #pragma unroll
    for (int e = ln; e < DIM_; e += 32) s += p[e];
    #pragma unroll
    for (int o = 16; o > 0; o >>= 1) s += __shfl_xor_sync(0xffffffffu, s, o);
    if (ln == 0) g_mm[row] = s * (1.0f / DIM_);
}

// ---------------- inter ----------------
__global__ void inter_k(float* __restrict__ outp)
{
    int idx = blockIdx.x * blockDim.x + threadIdx.x;
    if (idx >= B_ * 256 * 256) return;
    int x = idx & 255, y = (idx >> 8) & 255, b = idx >> 16;
    float v = g_mm[b * (N_ - 1) + (y >> 4) * 16 + (x >> 4)];
    if (y >= 8 && y < 248 && x >= 8 && x < 248) {
        float sh = g_mm[b * (N_ - 1) + 256 + ((y - 8) >> 4) * 15 + ((x - 8) >> 4)];
        v = 0.5f * (v + sh);
    }
    outp[idx] = v;
}

// ---------------- launch ----------------
extern "C" void kernel_launch(void* const* d_in, const int* in_sizes, int n_in,
                              void* d_out, int out_size)
{
    const float* x    = (const float*)d_in[0];
    const float* mask = (const float*)d_in[1];
    const float* Wqkv = (const float*)d_in[2];
    const float* Wout = (const float*)d_in[3];
    const float* bout = (const float*)d_in[4];
    float* out = (float*)d_out;

    float *p_qkv, *p_qkvm, *p_out2, *p_m2;
    cudaGetSymbolAddress((void**)&p_qkv,  g_qkv);
    cudaGetSymbolAddress((void**)&p_qkvm, g_qkvm);
    cudaGetSymbolAddress((void**)&p_out2, g_out2);
    cudaGetSymbolAddress((void**)&p_m2,   g_m2);

    static bool attr_set = false;
    if (!attr_set) {
        cudaFuncSetAttribute(flash_attn, cudaFuncAttributeMaxDynamicSharedMemorySize,
                             FA_SMEM_WORDS * 4);
        attr_set = true;
    }

    // 1-2. qkv = x @ Wqkv^T ; qkv_m = mask @ |Wqkv|^T   (tf32)
    mma_gemm<false,false,false><<<dim3(QKV_/128, BN_/128), 256>>>(x,    Wqkv, nullptr, p_qkv,
        BN_, QKV_, DIM_, DIM_, DIM_, QKV_, 0, 0, 0);
    mma_gemm<true, false,false><<<dim3(QKV_/128, BN_/128), 256>>>(mask, Wqkv, nullptr, p_qkvm,
        BN_, QKV_, DIM_, DIM_, DIM_, QKV_, 0, 0, 0);
    // 3. updated flags
    updated_k<<<(BN_ + 7) / 8, 256>>>(mask);
    // 4. maxima
    reduce_max_k<<<(B_*H_*3*D_ + 255) / 256, 256>>>();
    // 5. modulate
    modulate_k<<<(SZ_BND + 255) / 256, 256>>>();
    // 6-8. fused attention (QK^T + online softmax + dual PV), scores never hit HBM
    flash_attn<<<dim3(4, BH_), 256, FA_SMEM_WORDS * 4>>>();
    // 9. blending
    blend_k<<<(SZ_BND + 255) / 256, 256>>>();
    // 10. channel means
    mm_k<<<(B_ * (N_ - 1) + 7) / 8, 256>>>();
    // 11. inter
    inter_k<<<(B_ * 65536 + 255) / 256, 256>>>(out + 2 * (size_t)SZ_BND);
    // 12-13. final projections (tf32) straight into d_out
    mma_gemm<false,true ,false><<<dim3(DIM_/128, BN_/128), 256>>>(p_out2, Wout, bout, out,
        BN_, DIM_, DIM_, DIM_, DIM_, DIM_, 0, 0, 0);
    mma_gemm<true, false,false><<<dim3(DIM_/128, BN_/128), 256>>>(p_m2,   Wout, nullptr, out + (size_t)SZ_BND,
        BN_, DIM_, DIM_, DIM_, DIM_, DIM_, 0, 0, 0);
}